// round 4
// baseline (speedup 1.0000x reference)
#include <cuda_runtime.h>
#include <cuda_bf16.h>
#include <cstdint>

// ---------------------------------------------------------------------------
// MTL2d_DeepSVDD: 3x (conv s2 + relu -> MHSA(relpos bias) + residual) -> pool -> linear
// B=32, heads=3, dims {16,32,64}, dh {5,10,21}, inner {15,30,63}, N {1024,256,64}
// ---------------------------------------------------------------------------

#define BATCH 32
#define HEADS 3

__device__ float g_z1[BATCH * 16 * 32 * 32];
__device__ float g_z2[BATCH * 32 * 16 * 16];
__device__ float g_z3[BATCH * 64 * 8 * 8];
__device__ float g_att[BATCH * 63 * 64 > BATCH * 15 * 1024 ? BATCH * 63 * 64 : BATCH * 15 * 1024];

// ---------------- packed f32x2 helpers (Blackwell FFMA2 path) --------------
__device__ __forceinline__ unsigned long long pk2(float x, float y) {
    unsigned long long r;
    asm("mov.b64 %0, {%1, %2};" : "=l"(r) : "f"(x), "f"(y));
    return r;
}
__device__ __forceinline__ void upk2(unsigned long long v, float& x, float& y) {
    asm("mov.b64 {%0, %1}, %2;" : "=f"(x), "=f"(y) : "l"(v));
}
__device__ __forceinline__ unsigned long long fma2(unsigned long long a,
                                                   unsigned long long b,
                                                   unsigned long long c) {
    unsigned long long d;
    asm("fma.rn.f32x2 %0, %1, %2, %3;" : "=l"(d) : "l"(a), "l"(b), "l"(c));
    return d;
}
__device__ __forceinline__ unsigned long long mul2(unsigned long long a,
                                                   unsigned long long b) {
    unsigned long long d;
    asm("mul.rn.f32x2 %0, %1, %2;" : "=l"(d) : "l"(a), "l"(b));
    return d;
}
__device__ __forceinline__ unsigned long long add2(unsigned long long a,
                                                   unsigned long long b) {
    unsigned long long d;
    asm("add.rn.f32x2 %0, %1, %2;" : "=l"(d) : "l"(a), "l"(b));
    return d;
}
__device__ __forceinline__ float ex2f(float x) {
    float y;
    asm("ex2.approx.ftz.f32 %0, %1;" : "=f"(y) : "f"(x));
    return y;
}

// ---------------------------------------------------------------------------
// direct 3x3 stride-2 conv, pad 1, + bias + relu
// ---------------------------------------------------------------------------
template<int CIN, int COUT, int HIN, int HOUT>
__global__ void conv_s2_relu(const float* __restrict__ x,
                             const float* __restrict__ w,
                             const float* __restrict__ bias,
                             float* __restrict__ y) {
    int idx = blockIdx.x * blockDim.x + threadIdx.x;
    constexpr int TOTAL = BATCH * COUT * HOUT * HOUT;
    if (idx >= TOTAL) return;
    int ox = idx % HOUT;
    int t  = idx / HOUT;
    int oy = t % HOUT; t /= HOUT;
    int co = t % COUT;
    int b  = t / COUT;

    float s = bias[co];
    const float* xb = x + (size_t)b * CIN * HIN * HIN;
    const float* wc = w + (size_t)co * CIN * 9;
    #pragma unroll 4
    for (int ci = 0; ci < CIN; ci++) {
        #pragma unroll
        for (int ky = 0; ky < 3; ky++) {
            int iy = oy * 2 - 1 + ky;
            if ((unsigned)iy >= (unsigned)HIN) continue;
            #pragma unroll
            for (int kx = 0; kx < 3; kx++) {
                int ix = ox * 2 - 1 + kx;
                if ((unsigned)ix >= (unsigned)HIN) continue;
                s += xb[(ci * HIN + iy) * HIN + ix] * wc[ci * 9 + ky * 3 + kx];
            }
        }
    }
    y[idx] = fmaxf(s, 0.0f);
}

// ---------------------------------------------------------------------------
// fused attention: block = (b, h, q-slice). QKV computed IN-BLOCK from z
// (fuses the 1x1 qkv projection): z chunks staged in SMEM, K/V (+bias) for
// the whole head and pre-scaled Q for this block's queries written to SMEM.
// Then flash attention: each warp handles TQ queries; lanes own j-pairs
// (packed f32x2), online softmax in log2 domain, de-headed pre-scaled bias
// table in SMEM. qkv_w rows: q=dd*HEADS+h, k=INNER+..., v=2*INNER+...
// ---------------------------------------------------------------------------
template<int N, int C, int D, int HH, int QBLK, int TQ, int CW>
__global__ void __launch_bounds__(256, 2)
attn_fused(const float* __restrict__ z,
           const float* __restrict__ wqkv,
           const float* __restrict__ bqkv,
           const float* __restrict__ table,
           float* __restrict__ o_out) {
    constexpr int INNER = 3 * D;
    constexpr int QPB = N / QBLK;             // == CW in all instantiations
    constexpr int NPASS = QPB / (8 * TQ);
    constexpr int U = CW / 64;
    constexpr int TW = 2 * HH - 1;

    extern __shared__ float smem[];
    float* sk = smem;                  // D * N
    float* sv = sk + D * N;            // D * N
    float* st = sv + D * N;            // TW * TW  (pre-scaled bias)
    float* sq = st + TW * TW;          // D * QPB  (pre-scaled q)
    float* zb = sq + D * QPB;          // C * CW   (z chunk)

    int qsec = blockIdx.x % QBLK;
    int bh   = blockIdx.x / QBLK;
    int b = bh / HEADS, h = bh % HEADS;
    const float* zbase = z + (size_t)b * C * N;

    const float scl = rsqrtf((float)D) * 1.4426950408889634f;  // scale*log2e
    int tid = threadIdx.x;

    // ---- bias table (de-headed, pre-scaled) ----
    for (int i = tid; i < TW * TW; i += 256)
        st[i] = table[i * HEADS + h] * scl;

    // ---- phase A: Q for this block's query window ----
    int q0 = qsec * QPB;
    for (int i = tid; i < C * CW; i += 256)
        zb[i] = zbase[(i / CW) * N + q0 + (i % CW)];
    __syncthreads();
    for (int i = tid; i < D * CW; i += 256) {
        int dd = i / CW, col = i % CW;
        int row = dd * HEADS + h;
        float acc = bqkv[row];
        const float* wr = wqkv + row * C;
        #pragma unroll
        for (int c = 0; c < C; c++) acc += wr[c] * zb[c * CW + col];
        sq[dd * QPB + col] = acc * scl;
    }
    __syncthreads();

    // ---- phase B: K/V for the whole head, chunk by chunk ----
    for (int base = 0; base < N; base += CW) {
        for (int i = tid; i < C * CW; i += 256)
            zb[i] = zbase[(i / CW) * N + base + (i % CW)];
        __syncthreads();
        for (int i = tid; i < D * CW; i += 256) {
            int dd = i / CW, col = i % CW;
            int krow = INNER + dd * HEADS + h;
            int vrow = 2 * INNER + dd * HEADS + h;
            float ka = bqkv[krow], va = bqkv[vrow];
            const float* wkr = wqkv + (size_t)krow * C;
            const float* wvr = wqkv + (size_t)vrow * C;
            #pragma unroll
            for (int c = 0; c < C; c++) {
                float zv = zb[c * CW + col];
                ka += wkr[c] * zv;
                va += wvr[c] * zv;
            }
            sk[dd * N + base + col] = ka;
            sv[dd * N + base + col] = va;
        }
        __syncthreads();
    }

    int warp = tid >> 5, lane = tid & 31;

    for (int pass = 0; pass < NPASS; pass++) {
        int qr0 = (pass * 8 + warp) * TQ;       // relative to block
        int qg0 = q0 + qr0;                      // global

        unsigned long long qd[TQ][D];
        int At[TQ];
        #pragma unroll
        for (int t = 0; t < TQ; t++) {
            int qg = qg0 + t;
            #pragma unroll
            for (int dd = 0; dd < D; dd++) {
                float qv = sq[dd * QPB + qr0 + t];
                qd[t][dd] = pk2(qv, qv);
            }
            int yq = qg / HH, xq = qg % HH;
            At[t] = (yq + HH - 1) * TW + xq + HH - 1;
        }

        float m[TQ];
        unsigned long long l2[TQ];
        unsigned long long acc[TQ][D];
        #pragma unroll
        for (int t = 0; t < TQ; t++) {
            m[t] = -1e30f; l2[t] = 0ull;
            #pragma unroll
            for (int dd = 0; dd < D; dd++) acc[t][dd] = 0ull;
        }

        for (int c0 = 0; c0 < N; c0 += 64 * U) {
            unsigned long long s[TQ][U];
            // ---- score pass ----
            #pragma unroll
            for (int u = 0; u < U; u++) {
                int j  = c0 + u * 64 + lane * 2;
                int yk = j / HH, xk = j % HH;   // even j, even HH => pair shares row
                int off = yk * TW + xk;
                unsigned long long k2[D];
                #pragma unroll
                for (int dd = 0; dd < D; dd++)
                    k2[dd] = *(const unsigned long long*)&sk[dd * N + j];
                #pragma unroll
                for (int t = 0; t < TQ; t++) {
                    int ri = At[t] - off;
                    unsigned long long sc = pk2(st[ri], st[ri - 1]);
                    #pragma unroll
                    for (int dd = 0; dd < D; dd++)
                        sc = fma2(qd[t][dd], k2[dd], sc);
                    s[t][u] = sc;
                }
            }
            // ---- online max / rescale ----
            #pragma unroll
            for (int t = 0; t < TQ; t++) {
                float mx = m[t];
                #pragma unroll
                for (int u = 0; u < U; u++) {
                    float a, bb; upk2(s[t][u], a, bb);
                    mx = fmaxf(mx, fmaxf(a, bb));
                }
                if (mx > m[t]) {
                    float corr = ex2f(m[t] - mx);
                    unsigned long long c2 = pk2(corr, corr);
                    l2[t] = mul2(l2[t], c2);
                    #pragma unroll
                    for (int dd = 0; dd < D; dd++) acc[t][dd] = mul2(acc[t][dd], c2);
                    m[t] = mx;
                }
            }
            // ---- exp + AV pass ----
            #pragma unroll
            for (int u = 0; u < U; u++) {
                int j = c0 + u * 64 + lane * 2;
                unsigned long long v2[D];
                #pragma unroll
                for (int dd = 0; dd < D; dd++)
                    v2[dd] = *(const unsigned long long*)&sv[dd * N + j];
                #pragma unroll
                for (int t = 0; t < TQ; t++) {
                    float a, bb; upk2(s[t][u], a, bb);
                    float px = ex2f(a - m[t]);
                    float py = ex2f(bb - m[t]);
                    unsigned long long p2 = pk2(px, py);
                    l2[t] = add2(l2[t], p2);
                    #pragma unroll
                    for (int dd = 0; dd < D; dd++)
                        acc[t][dd] = fma2(p2, v2[dd], acc[t][dd]);
                }
            }
        }

        // ---- cross-lane combine & write ----
        #pragma unroll
        for (int t = 0; t < TQ; t++) {
            int qg = qg0 + t;
            float gm = m[t];
            #pragma unroll
            for (int off = 16; off; off >>= 1)
                gm = fmaxf(gm, __shfl_xor_sync(0xffffffffu, gm, off));
            float cf = ex2f(m[t] - gm);
            float lx, ly; upk2(l2[t], lx, ly);
            float ls = (lx + ly) * cf;
            #pragma unroll
            for (int off = 16; off; off >>= 1)
                ls += __shfl_xor_sync(0xffffffffu, ls, off);
            float inv = 1.0f / ls;
            #pragma unroll
            for (int dd = 0; dd < D; dd++) {
                float ax, ay; upk2(acc[t][dd], ax, ay);
                float a = (ax + ay) * cf;
                #pragma unroll
                for (int off = 16; off; off >>= 1)
                    a += __shfl_xor_sync(0xffffffffu, a, off);
                if (lane == 0)
                    o_out[((size_t)b * INNER + dd * HEADS + h) * N + qg] = a * inv;
            }
        }
    }
}

// ---------------------------------------------------------------------------
// out projection + residual (in-place on z), float4-vectorized along n
// ---------------------------------------------------------------------------
template<int INNER, int DIM, int N>
__global__ void outproj_res(const float* __restrict__ o,
                            const float* __restrict__ w,
                            const float* __restrict__ bias,
                            float* __restrict__ z) {
    int idx = blockIdx.x * blockDim.x + threadIdx.x;
    constexpr int N4 = N / 4;
    constexpr int TOTAL4 = BATCH * DIM * N4;
    if (idx >= TOTAL4) return;
    int n4 = idx % N4;
    int t  = idx / N4;
    int c = t % DIM;
    int b = t / DIM;
    float4 s = ((float4*)z)[idx];
    float bc = bias[c];
    s.x += bc; s.y += bc; s.z += bc; s.w += bc;
    const float4* ob = (const float4*)(o + (size_t)b * INNER * N);
    const float* wr = w + (size_t)c * INNER;
    #pragma unroll
    for (int i = 0; i < INNER; i++) {
        float wv = wr[i];
        float4 ov = ob[i * N4 + n4];
        s.x += wv * ov.x; s.y += wv * ov.y; s.z += wv * ov.z; s.w += wv * ov.w;
    }
    ((float4*)z)[idx] = s;
}

// ---------------------------------------------------------------------------
// mean pool + classifier
// ---------------------------------------------------------------------------
__global__ void pool_cls(const float* __restrict__ z3,
                         const float* __restrict__ cw,
                         const float* __restrict__ cb,
                         float* __restrict__ out) {
    int b = blockIdx.x;
    int c = threadIdx.x;
    __shared__ float m[64];
    const float* zb = z3 + ((size_t)b * 64 + c) * 64;
    float s = 0.0f;
    #pragma unroll
    for (int n = 0; n < 64; n++) s += zb[n];
    s *= (1.0f / 64.0f);
    m[c] = s;
    out[b * 64 + c] = s;
    __syncthreads();
    if (c < 10) {
        float t = cb[c];
        #pragma unroll
        for (int k = 0; k < 64; k++) t += cw[c * 64 + k] * m[k];
        out[BATCH * 64 + b * 10 + c] = t;
    }
}

// ---------------------------------------------------------------------------

static inline int blocks(int total, int tpb) { return (total + tpb - 1) / tpb; }

// smem floats: 2*D*N + TW*TW + D*QPB + C*CW
template<int N, int C, int D, int HH, int QBLK, int CW>
static constexpr int attn_smem_bytes() {
    return (2 * D * N + (2 * HH - 1) * (2 * HH - 1) + D * (N / QBLK) + C * CW) * 4;
}

extern "C" void kernel_launch(void* const* d_in, const int* in_sizes, int n_in,
                              void* d_out, int out_size) {
    const float* x       = (const float*)d_in[0];
    const float* conv1_w = (const float*)d_in[1];
    const float* conv1_b = (const float*)d_in[2];
    const float* qkv1_w  = (const float*)d_in[3];
    const float* qkv1_b  = (const float*)d_in[4];
    const float* out1_w  = (const float*)d_in[5];
    const float* out1_b  = (const float*)d_in[6];
    const float* rel1    = (const float*)d_in[7];
    const float* conv2_w = (const float*)d_in[8];
    const float* conv2_b = (const float*)d_in[9];
    const float* qkv2_w  = (const float*)d_in[10];
    const float* qkv2_b  = (const float*)d_in[11];
    const float* out2_w  = (const float*)d_in[12];
    const float* out2_b  = (const float*)d_in[13];
    const float* rel2    = (const float*)d_in[14];
    const float* conv3_w = (const float*)d_in[15];
    const float* conv3_b = (const float*)d_in[16];
    const float* qkv3_w  = (const float*)d_in[17];
    const float* qkv3_b  = (const float*)d_in[18];
    const float* out3_w  = (const float*)d_in[19];
    const float* out3_b  = (const float*)d_in[20];
    const float* rel3    = (const float*)d_in[21];
    const float* cls_w   = (const float*)d_in[22];
    const float* cls_b   = (const float*)d_in[23];
    float* out = (float*)d_out;

    float *z1, *z2, *z3, *att;
    cudaGetSymbolAddress((void**)&z1,  g_z1);
    cudaGetSymbolAddress((void**)&z2,  g_z2);
    cudaGetSymbolAddress((void**)&z3,  g_z3);
    cudaGetSymbolAddress((void**)&att, g_att);

    const int TPB = 256;

    constexpr int SM1 = attn_smem_bytes<1024, 16, 5, 32, 8, 128>();
    constexpr int SM2 = attn_smem_bytes<256, 32, 10, 16, 2, 128>();
    constexpr int SM3 = attn_smem_bytes<64, 64, 21, 8, 1, 64>();
    cudaFuncSetAttribute((const void*)attn_fused<1024, 16, 5, 32, 8, 4, 128>,
                         cudaFuncAttributeMaxDynamicSharedMemorySize, SM1);
    cudaFuncSetAttribute((const void*)attn_fused<256, 32, 10, 16, 2, 2, 128>,
                         cudaFuncAttributeMaxDynamicSharedMemorySize, SM2);
    cudaFuncSetAttribute((const void*)attn_fused<64, 64, 21, 8, 1, 1, 64>,
                         cudaFuncAttributeMaxDynamicSharedMemorySize, SM3);

    // ---- stage 1: N=1024, C=16, d=5 ----
    conv_s2_relu<1, 16, 64, 32><<<blocks(BATCH*16*32*32, TPB), TPB>>>(x, conv1_w, conv1_b, z1);
    attn_fused<1024, 16, 5, 32, 8, 4, 128><<<BATCH*HEADS*8, 256, SM1>>>(z1, qkv1_w, qkv1_b, rel1, att);
    outproj_res<15, 16, 1024><<<blocks(BATCH*16*256, TPB), TPB>>>(att, out1_w, out1_b, z1);

    // ---- stage 2: N=256, C=32, d=10 ----
    conv_s2_relu<16, 32, 32, 16><<<blocks(BATCH*32*16*16, TPB), TPB>>>(z1, conv2_w, conv2_b, z2);
    attn_fused<256, 32, 10, 16, 2, 2, 128><<<BATCH*HEADS*2, 256, SM2>>>(z2, qkv2_w, qkv2_b, rel2, att);
    outproj_res<30, 32, 256><<<blocks(BATCH*32*64, TPB), TPB>>>(att, out2_w, out2_b, z2);

    // ---- stage 3: N=64, C=64, d=21 ----
    conv_s2_relu<32, 64, 16, 8><<<blocks(BATCH*64*8*8, TPB), TPB>>>(z2, conv3_w, conv3_b, z3);
    attn_fused<64, 64, 21, 8, 1, 1, 64><<<BATCH*HEADS, 256, SM3>>>(z3, qkv3_w, qkv3_b, rel3, att);
    outproj_res<63, 64, 64><<<blocks(BATCH*64*16, TPB), TPB>>>(att, out3_w, out3_b, z3);

    // ---- pool + classifier ----
    pool_cls<<<BATCH, 64>>>(z3, cls_w, cls_b, out);
}

// round 5
// speedup vs baseline: 1.1698x; 1.1698x over previous
#include <cuda_runtime.h>
#include <cuda_bf16.h>
#include <cstdint>

// ---------------------------------------------------------------------------
// MTL2d_DeepSVDD: 3x (conv s2 + relu -> MHSA(relpos bias) + residual) -> pool -> linear
// B=32, heads=3, dims {16,32,64}, dh {5,10,21}, inner {15,30,63}, N {1024,256,64}
// ---------------------------------------------------------------------------

#define BATCH 32
#define HEADS 3

__device__ float g_z1[BATCH * 16 * 32 * 32];
__device__ float g_z2[BATCH * 32 * 16 * 16];
__device__ float g_z3[BATCH * 64 * 8 * 8];
__device__ float g_qkv[BATCH * 45 * 1024];
__device__ float g_att[BATCH * 15 * 1024];

// ---------------- packed f32x2 helpers (Blackwell FFMA2 path) --------------
__device__ __forceinline__ unsigned long long pk2(float x, float y) {
    unsigned long long r;
    asm("mov.b64 %0, {%1, %2};" : "=l"(r) : "f"(x), "f"(y));
    return r;
}
__device__ __forceinline__ void upk2(unsigned long long v, float& x, float& y) {
    asm("mov.b64 {%0, %1}, %2;" : "=f"(x), "=f"(y) : "l"(v));
}
__device__ __forceinline__ unsigned long long fma2(unsigned long long a,
                                                   unsigned long long b,
                                                   unsigned long long c) {
    unsigned long long d;
    asm("fma.rn.f32x2 %0, %1, %2, %3;" : "=l"(d) : "l"(a), "l"(b), "l"(c));
    return d;
}
__device__ __forceinline__ unsigned long long mul2(unsigned long long a,
                                                   unsigned long long b) {
    unsigned long long d;
    asm("mul.rn.f32x2 %0, %1, %2;" : "=l"(d) : "l"(a), "l"(b));
    return d;
}
__device__ __forceinline__ unsigned long long add2(unsigned long long a,
                                                   unsigned long long b) {
    unsigned long long d;
    asm("add.rn.f32x2 %0, %1, %2;" : "=l"(d) : "l"(a), "l"(b));
    return d;
}
__device__ __forceinline__ float ex2f(float x) {
    float y;
    asm("ex2.approx.ftz.f32 %0, %1;" : "=f"(y) : "f"(x));
    return y;
}

// ---------------------------------------------------------------------------
// conv 3x3 stride-2 pad-1 + bias + relu, v2:
//  - weights repacked in SMEM as [ci*9+k][co] (co fastest) -> LDS.64 = packed pair
//  - each thread: 4 output channels x OXPT output pixels, packed fma2
// ---------------------------------------------------------------------------
template<int CIN, int COUT, int HIN, int HOUT, int OXPT>
__global__ void __launch_bounds__(256)
conv_s2_relu_v2(const float* __restrict__ x,
                const float* __restrict__ w,
                const float* __restrict__ bias,
                float* __restrict__ y) {
    extern __shared__ float sw[];   // [(CIN*9)][COUT]
    int tid = threadIdx.x;
    for (int i = tid; i < COUT * CIN * 9; i += 256) {
        int co = i / (CIN * 9);
        int r  = i % (CIN * 9);
        sw[r * COUT + co] = w[i];
    }
    __syncthreads();

    constexpr int OXG = HOUT / OXPT;
    int idx = blockIdx.x * 256 + tid;
    int oxp = idx % OXG;
    int t   = idx / OXG;
    int oy  = t % HOUT; t /= HOUT;
    int cog = t % (COUT / 4);
    int b   = t / (COUT / 4);

    int c0  = cog * 4;
    int ox0 = oxp * OXPT;
    const float* xb = x + (size_t)b * CIN * HIN * HIN;

    unsigned long long a0p = pk2(bias[c0], bias[c0 + 1]);
    unsigned long long a0q = pk2(bias[c0 + 2], bias[c0 + 3]);
    unsigned long long a1p = a0p, a1q = a0q;

    constexpr int NX = (OXPT == 2) ? 5 : 3;
    int ixb = ox0 * 2 - 1;

    for (int ci = 0; ci < CIN; ci++) {
        #pragma unroll
        for (int ky = 0; ky < 3; ky++) {
            int iy = oy * 2 - 1 + ky;
            if ((unsigned)iy >= (unsigned)HIN) continue;
            const float* row = xb + (ci * HIN + iy) * HIN;
            float xv[NX];
            #pragma unroll
            for (int u = 0; u < NX; u++) {
                int ix = ixb + u;
                xv[u] = ((unsigned)ix < (unsigned)HIN) ? row[ix] : 0.0f;
            }
            const float* wp = &sw[(ci * 9 + ky * 3) * COUT + c0];
            #pragma unroll
            for (int kx = 0; kx < 3; kx++) {
                unsigned long long w01 = *(const unsigned long long*)(wp + kx * COUT);
                unsigned long long w23 = *(const unsigned long long*)(wp + kx * COUT + 2);
                unsigned long long x0 = pk2(xv[kx], xv[kx]);
                a0p = fma2(x0, w01, a0p);
                a0q = fma2(x0, w23, a0q);
                if (OXPT == 2) {
                    unsigned long long x1 = pk2(xv[kx + 2], xv[kx + 2]);
                    a1p = fma2(x1, w01, a1p);
                    a1q = fma2(x1, w23, a1q);
                }
            }
        }
    }

    float v0[4], v1[4];
    upk2(a0p, v0[0], v0[1]); upk2(a0q, v0[2], v0[3]);
    upk2(a1p, v1[0], v1[1]); upk2(a1q, v1[2], v1[3]);
    #pragma unroll
    for (int r = 0; r < 4; r++) {
        size_t o = (((size_t)b * COUT + c0 + r) * HOUT + oy) * HOUT + ox0;
        if (OXPT == 2) {
            float2 st2 = make_float2(fmaxf(v0[r], 0.0f), fmaxf(v1[r], 0.0f));
            *(float2*)(y + o) = st2;
        } else {
            y[o] = fmaxf(v0[r], 0.0f);
        }
    }
}

// ---------------------------------------------------------------------------
// 1x1 projection, float4-vectorized along n
// ---------------------------------------------------------------------------
template<int C, int O, int N>
__global__ void proj1x1(const float* __restrict__ z,
                        const float* __restrict__ w,
                        const float* __restrict__ bias,
                        float* __restrict__ y) {
    int idx = blockIdx.x * blockDim.x + threadIdx.x;
    constexpr int N4 = N / 4;
    constexpr int TOTAL4 = BATCH * O * N4;
    if (idx >= TOTAL4) return;
    int n4 = idx % N4;
    int t  = idx / N4;
    int o = t % O;
    int b = t / O;
    float bo = bias[o];
    float4 s = make_float4(bo, bo, bo, bo);
    const float4* zb = (const float4*)(z + (size_t)b * C * N);
    const float* wr = w + (size_t)o * C;
    #pragma unroll
    for (int c = 0; c < C; c++) {
        float wv = wr[c];
        float4 zv = zb[c * N4 + n4];
        s.x += wv * zv.x; s.y += wv * zv.y; s.z += wv * zv.z; s.w += wv * zv.w;
    }
    ((float4*)y)[idx] = s;
}

// ---------------------------------------------------------------------------
// flash attention (round-3 design): block = (b, h, q-slice). K,V + de-headed
// pre-scaled bias table staged in SMEM. Each warp: TQ queries; lanes own
// j-pairs (packed f32x2). Online softmax in log2 domain.
// ---------------------------------------------------------------------------
template<int N, int D, int HH, int QBLK, int TQ>
__global__ void __launch_bounds__(256, 2)
attn_flash(const float* __restrict__ qkv,
           const float* __restrict__ table,
           float* __restrict__ o_out) {
    constexpr int INNER = 3 * D;
    constexpr int QPB = N / QBLK;
    constexpr int NPASS = QPB / (8 * TQ);
    constexpr int U = (N >= 128) ? 2 : 1;
    constexpr int TW = 2 * HH - 1;

    __shared__ float sk[D][N];
    __shared__ float sv[D][N];
    __shared__ float st[TW * TW];

    int qsec = blockIdx.x % QBLK;
    int bh   = blockIdx.x / QBLK;
    int b = bh / HEADS, h = bh % HEADS;
    const float* base = qkv + (size_t)b * 3 * INNER * N;

    const float scl = rsqrtf((float)D) * 1.4426950408889634f;

    int tid = threadIdx.x;
    for (int i = tid; i < D * (N / 4); i += 256) {
        int dd = i / (N / 4);
        int j4 = i % (N / 4);
        const float4* kr = (const float4*)(base + (size_t)(INNER + dd * HEADS + h) * N);
        const float4* vr = (const float4*)(base + (size_t)(2 * INNER + dd * HEADS + h) * N);
        ((float4*)&sk[dd][0])[j4] = kr[j4];
        ((float4*)&sv[dd][0])[j4] = vr[j4];
    }
    for (int i = tid; i < TW * TW; i += 256)
        st[i] = table[i * HEADS + h] * scl;
    __syncthreads();

    int warp = tid >> 5, lane = tid & 31;

    for (int pass = 0; pass < NPASS; pass++) {
        int q0 = qsec * QPB + (pass * 8 + warp) * TQ;

        unsigned long long qd[TQ][D];
        int At[TQ];
        #pragma unroll
        for (int t = 0; t < TQ; t++) {
            int q = q0 + t;
            #pragma unroll
            for (int dd = 0; dd < D; dd++) {
                float qv = base[(dd * HEADS + h) * N + q] * scl;
                qd[t][dd] = pk2(qv, qv);
            }
            int yq = q / HH, xq = q % HH;
            At[t] = (yq + HH - 1) * TW + xq + HH - 1;
        }

        float m[TQ];
        unsigned long long l2[TQ];
        unsigned long long acc[TQ][D];
        #pragma unroll
        for (int t = 0; t < TQ; t++) {
            m[t] = -1e30f; l2[t] = 0ull;
            #pragma unroll
            for (int dd = 0; dd < D; dd++) acc[t][dd] = 0ull;
        }

        for (int c0 = 0; c0 < N; c0 += 64 * U) {
            unsigned long long s[TQ][U];
            #pragma unroll
            for (int u = 0; u < U; u++) {
                int j  = c0 + u * 64 + lane * 2;
                int yk = j / HH, xk = j % HH;
                int off = yk * TW + xk;
                unsigned long long k2[D];
                #pragma unroll
                for (int dd = 0; dd < D; dd++)
                    k2[dd] = *(const unsigned long long*)&sk[dd][j];
                #pragma unroll
                for (int t = 0; t < TQ; t++) {
                    int ri = At[t] - off;
                    unsigned long long sc = pk2(st[ri], st[ri - 1]);
                    #pragma unroll
                    for (int dd = 0; dd < D; dd++)
                        sc = fma2(qd[t][dd], k2[dd], sc);
                    s[t][u] = sc;
                }
            }
            #pragma unroll
            for (int t = 0; t < TQ; t++) {
                float mx = m[t];
                #pragma unroll
                for (int u = 0; u < U; u++) {
                    float a, bb; upk2(s[t][u], a, bb);
                    mx = fmaxf(mx, fmaxf(a, bb));
                }
                if (mx > m[t]) {
                    float corr = ex2f(m[t] - mx);
                    unsigned long long c2 = pk2(corr, corr);
                    l2[t] = mul2(l2[t], c2);
                    #pragma unroll
                    for (int dd = 0; dd < D; dd++) acc[t][dd] = mul2(acc[t][dd], c2);
                    m[t] = mx;
                }
            }
            #pragma unroll
            for (int u = 0; u < U; u++) {
                int j = c0 + u * 64 + lane * 2;
                unsigned long long v2[D];
                #pragma unroll
                for (int dd = 0; dd < D; dd++)
                    v2[dd] = *(const unsigned long long*)&sv[dd][j];
                #pragma unroll
                for (int t = 0; t < TQ; t++) {
                    float a, bb; upk2(s[t][u], a, bb);
                    float px = ex2f(a - m[t]);
                    float py = ex2f(bb - m[t]);
                    unsigned long long p2 = pk2(px, py);
                    l2[t] = add2(l2[t], p2);
                    #pragma unroll
                    for (int dd = 0; dd < D; dd++)
                        acc[t][dd] = fma2(p2, v2[dd], acc[t][dd]);
                }
            }
        }

        #pragma unroll
        for (int t = 0; t < TQ; t++) {
            int q = q0 + t;
            float gm = m[t];
            #pragma unroll
            for (int off = 16; off; off >>= 1)
                gm = fmaxf(gm, __shfl_xor_sync(0xffffffffu, gm, off));
            float cf = ex2f(m[t] - gm);
            float lx, ly; upk2(l2[t], lx, ly);
            float ls = (lx + ly) * cf;
            #pragma unroll
            for (int off = 16; off; off >>= 1)
                ls += __shfl_xor_sync(0xffffffffu, ls, off);
            float inv = 1.0f / ls;
            #pragma unroll
            for (int dd = 0; dd < D; dd++) {
                float ax, ay; upk2(acc[t][dd], ax, ay);
                float a = (ax + ay) * cf;
                #pragma unroll
                for (int off = 16; off; off >>= 1)
                    a += __shfl_xor_sync(0xffffffffu, a, off);
                if (lane == 0)
                    o_out[((size_t)b * INNER + dd * HEADS + h) * N + q] = a * inv;
            }
        }
    }
}

// ---------------------------------------------------------------------------
// out projection + residual (in-place on z), float4-vectorized along n
// ---------------------------------------------------------------------------
template<int INNER, int DIM, int N>
__global__ void outproj_res(const float* __restrict__ o,
                            const float* __restrict__ w,
                            const float* __restrict__ bias,
                            float* __restrict__ z) {
    int idx = blockIdx.x * blockDim.x + threadIdx.x;
    constexpr int N4 = N / 4;
    constexpr int TOTAL4 = BATCH * DIM * N4;
    if (idx >= TOTAL4) return;
    int n4 = idx % N4;
    int t  = idx / N4;
    int c = t % DIM;
    int b = t / DIM;
    float4 s = ((float4*)z)[idx];
    float bc = bias[c];
    s.x += bc; s.y += bc; s.z += bc; s.w += bc;
    const float4* ob = (const float4*)(o + (size_t)b * INNER * N);
    const float* wr = w + (size_t)c * INNER;
    #pragma unroll
    for (int i = 0; i < INNER; i++) {
        float wv = wr[i];
        float4 ov = ob[i * N4 + n4];
        s.x += wv * ov.x; s.y += wv * ov.y; s.z += wv * ov.z; s.w += wv * ov.w;
    }
    ((float4*)z)[idx] = s;
}

// ---------------------------------------------------------------------------
// mean pool + classifier
// ---------------------------------------------------------------------------
__global__ void pool_cls(const float* __restrict__ z3,
                         const float* __restrict__ cw,
                         const float* __restrict__ cb,
                         float* __restrict__ out) {
    int b = blockIdx.x;
    int c = threadIdx.x;
    __shared__ float m[64];
    const float* zb = z3 + ((size_t)b * 64 + c) * 64;
    float s = 0.0f;
    #pragma unroll
    for (int n = 0; n < 64; n++) s += zb[n];
    s *= (1.0f / 64.0f);
    m[c] = s;
    out[b * 64 + c] = s;
    __syncthreads();
    if (c < 10) {
        float t = cb[c];
        #pragma unroll
        for (int k = 0; k < 64; k++) t += cw[c * 64 + k] * m[k];
        out[BATCH * 64 + b * 10 + c] = t;
    }
}

// ---------------------------------------------------------------------------

static inline int blocks(int total, int tpb) { return (total + tpb - 1) / tpb; }

extern "C" void kernel_launch(void* const* d_in, const int* in_sizes, int n_in,
                              void* d_out, int out_size) {
    const float* x       = (const float*)d_in[0];
    const float* conv1_w = (const float*)d_in[1];
    const float* conv1_b = (const float*)d_in[2];
    const float* qkv1_w  = (const float*)d_in[3];
    const float* qkv1_b  = (const float*)d_in[4];
    const float* out1_w  = (const float*)d_in[5];
    const float* out1_b  = (const float*)d_in[6];
    const float* rel1    = (const float*)d_in[7];
    const float* conv2_w = (const float*)d_in[8];
    const float* conv2_b = (const float*)d_in[9];
    const float* qkv2_w  = (const float*)d_in[10];
    const float* qkv2_b  = (const float*)d_in[11];
    const float* out2_w  = (const float*)d_in[12];
    const float* out2_b  = (const float*)d_in[13];
    const float* rel2    = (const float*)d_in[14];
    const float* conv3_w = (const float*)d_in[15];
    const float* conv3_b = (const float*)d_in[16];
    const float* qkv3_w  = (const float*)d_in[17];
    const float* qkv3_b  = (const float*)d_in[18];
    const float* out3_w  = (const float*)d_in[19];
    const float* out3_b  = (const float*)d_in[20];
    const float* rel3    = (const float*)d_in[21];
    const float* cls_w   = (const float*)d_in[22];
    const float* cls_b   = (const float*)d_in[23];
    float* out = (float*)d_out;

    float *z1, *z2, *z3, *qkv, *att;
    cudaGetSymbolAddress((void**)&z1,  g_z1);
    cudaGetSymbolAddress((void**)&z2,  g_z2);
    cudaGetSymbolAddress((void**)&z3,  g_z3);
    cudaGetSymbolAddress((void**)&qkv, g_qkv);
    cudaGetSymbolAddress((void**)&att, g_att);

    const int TPB = 256;

    // conv smem sizes (weights repack)
    constexpr int CS1 = 16 * 1 * 9 * 4;      // 576 B
    constexpr int CS2 = 32 * 16 * 9 * 4;     // 18432 B
    constexpr int CS3 = 64 * 32 * 9 * 4;     // 73728 B (needs attribute)
    cudaFuncSetAttribute((const void*)conv_s2_relu_v2<32, 64, 16, 8, 1>,
                         cudaFuncAttributeMaxDynamicSharedMemorySize, CS3);

    // ---- stage 1: N=1024, C=16, d=5 ----
    conv_s2_relu_v2<1, 16, 64, 32, 2><<<BATCH*4*32*16/256, 256, CS1>>>(x, conv1_w, conv1_b, z1);
    proj1x1<16, 45, 1024><<<blocks(BATCH*45*256, TPB), TPB>>>(z1, qkv1_w, qkv1_b, qkv);
    attn_flash<1024, 5, 32, 8, 4><<<BATCH*HEADS*8, 256>>>(qkv, rel1, att);
    outproj_res<15, 16, 1024><<<blocks(BATCH*16*256, TPB), TPB>>>(att, out1_w, out1_b, z1);

    // ---- stage 2: N=256, C=32, d=10 ----
    conv_s2_relu_v2<16, 32, 32, 16, 2><<<BATCH*8*16*8/256, 256, CS2>>>(z1, conv2_w, conv2_b, z2);
    proj1x1<32, 90, 256><<<blocks(BATCH*90*64, TPB), TPB>>>(z2, qkv2_w, qkv2_b, qkv);
    attn_flash<256, 10, 16, 2, 2><<<BATCH*HEADS*2, 256>>>(qkv, rel2, att);
    outproj_res<30, 32, 256><<<blocks(BATCH*32*64, TPB), TPB>>>(att, out2_w, out2_b, z2);

    // ---- stage 3: N=64, C=64, d=21 ----
    conv_s2_relu_v2<32, 64, 16, 8, 1><<<BATCH*16*8*8/256, 256, CS3>>>(z2, conv3_w, conv3_b, z3);
    proj1x1<64, 189, 64><<<blocks(BATCH*189*16, TPB), TPB>>>(z3, qkv3_w, qkv3_b, qkv);
    attn_flash<64, 21, 8, 1, 1><<<BATCH*HEADS, 256>>>(qkv, rel3, att);
    outproj_res<63, 64, 64><<<blocks(BATCH*64*16, TPB), TPB>>>(att, out3_w, out3_b, z3);

    // ---- pool + classifier ----
    pool_cls<<<BATCH, 64>>>(z3, cls_w, cls_b, out);
}